// round 15
// baseline (speedup 1.0000x reference)
#include <cuda_runtime.h>
#include <cuda_fp16.h>
#include <cstdint>
#include <cstddef>

#define NN 50000
#define EE 800000
#define DD 128
#define RR 8
#define BB 4
#define LL 2
#define KCAT 640               // 4 bases * 128 + 128 self-loop
#define BN_EPS 1e-3f

#define KCH 64                 // k-chunk depth
#define RS 72                  // smem row stride (elements), 144B
#define TILE_A_E (64 * RS)     // 64-row A tile
#define TILE_B_E (128 * RS)    // 128-row B tile
#define STAGE_E (TILE_A_E + TILE_B_E)       // A, B
#define SMEM_GEMM_TOTAL (2 * STAGE_E * 2)   // 55296 bytes (2 stages)

// ---------------- device scratch ----------------
__device__ __half  g_hA[(size_t)NN * DD];
__device__ __half  g_hB[(size_t)NN * DD];
__device__ __half  g_nf[(size_t)NN * DD];
__device__ __half  g_P[(size_t)NN * 512];
__device__ __half  g_Bc_h[2][(size_t)DD * KCAT];
__device__ __half  g_We_h[(size_t)DD * DD];
__device__ int     g_cnt[(size_t)NN * RR];   // node-major: cnt[n*8 + r]
__device__ float   g_nodenorm[NN];
__device__ int     g_deg[NN];
__device__ int     g_rowptr[NN + 1];
__device__ int     g_cursor[NN];
__device__ int     g_bsum[256];
__device__ int     g_edges[EE];

// ================= helpers =================
__device__ __forceinline__ uint32_t smem_u32(const void* p) {
    uint32_t a;
    asm("{ .reg .u64 t; cvta.to.shared.u64 t, %1; cvt.u32.u64 %0, t; }" : "=r"(a) : "l"(p));
    return a;
}
__device__ __forceinline__ void ldm_x4(uint32_t* r, uint32_t addr) {
    asm volatile("ldmatrix.sync.aligned.m8n8.x4.shared.b16 {%0,%1,%2,%3}, [%4];"
                 : "=r"(r[0]), "=r"(r[1]), "=r"(r[2]), "=r"(r[3]) : "r"(addr));
}
__device__ __forceinline__ void mma16816(float* d, const uint32_t* a, const uint32_t* b) {
    asm volatile("mma.sync.aligned.m16n8k16.row.col.f32.f16.f16.f32 "
                 "{%0,%1,%2,%3}, {%4,%5,%6,%7}, {%8,%9}, {%0,%1,%2,%3};"
                 : "+f"(d[0]), "+f"(d[1]), "+f"(d[2]), "+f"(d[3])
                 : "r"(a[0]), "r"(a[1]), "r"(a[2]), "r"(a[3]), "r"(b[0]), "r"(b[1]));
}
__device__ __forceinline__ void cp_async16(uint32_t d, const void* s, int sz) {
    asm volatile("cp.async.cg.shared.global [%0], [%1], 16, %2;"
                 :: "r"(d), "l"(__cvta_generic_to_global(s)), "r"(sz));
}
__device__ __forceinline__ uint32_t pack2h(float x0, float x1) {
    __half2 a = __floats2half2_rn(x0, x1);
    return *(uint32_t*)&a;
}
__device__ __forceinline__ uint2 pack4h(float4 v) {
    uint2 r;
    r.x = pack2h(v.x, v.y);
    r.y = pack2h(v.z, v.w);
    return r;
}

// ================= GEMM (HMMA fp16, single-term, 64x128 tiles) =========
struct Chunk { const __half *Ah, *Bh; int lda, ldb; };
struct GemmChunks { int n; Chunk c[10]; };

__global__ __launch_bounds__(256, 3)
void mma_gemm(GemmChunks ch,
              const float* __restrict__ bias,
              const float* __restrict__ bn_gamma, const float* __restrict__ bn_beta,
              const float* __restrict__ bn_mean, const float* __restrict__ bn_var,
              float* __restrict__ Cf, __half* __restrict__ Chi, int M) {
    extern __shared__ __half smem[];
    const int tid = threadIdx.x;
    const int wid = tid >> 5;
    const int lane = tid & 31;
    const int warp_m = wid >> 2;          // 0..1, 32 rows each
    const int warp_n = wid & 3;           // 0..3, 32 cols each
    const int m0 = blockIdx.y * 64;

    auto load_chunk = [&](int c, int st) {
        const Chunk ck = ch.c[c];
        __half* s0 = smem + st * STAGE_E;
        #pragma unroll
        for (int i = 0; i < 2; ++i) {
            int t = tid + i * 256;          // 0..511
            int row = t >> 3, kc = t & 7;
            int gr = m0 + row;
            int ok = (gr < M);
            size_t ga = (size_t)(ok ? gr : 0);
            cp_async16(smem_u32(s0 + row * RS + kc * 8),
                       ck.Ah + ga * ck.lda + kc * 8, ok ? 16 : 0);
        }
        #pragma unroll
        for (int i = 0; i < 4; ++i) {
            int t = tid + i * 256;
            int row = t >> 3, kc = t & 7;
            cp_async16(smem_u32(s0 + TILE_A_E + row * RS + kc * 8),
                       ck.Bh + (size_t)row * ck.ldb + kc * 8, 16);
        }
        asm volatile("cp.async.commit_group;" ::: "memory");
    };

    float acc[2][4][4];
    #pragma unroll
    for (int a = 0; a < 2; ++a)
        #pragma unroll
        for (int b = 0; b < 4; ++b)
            #pragma unroll
            for (int c = 0; c < 4; ++c) acc[a][b][c] = 0.f;

    const int a_row_off = (warp_m * 32 + (lane & 15)) * RS + ((lane >> 4) << 3);
    const int b_row_off = (warp_n * 32 + (lane & 7) + (((lane >> 4) & 1) << 3)) * RS
                          + (((lane >> 3) & 1) << 3);

    auto compute = [&](int st) {
        const uint32_t ub = smem_u32(smem + st * STAGE_E);
        const uint32_t uA = ub;
        const uint32_t uB = ub + (uint32_t)TILE_A_E * 2u;
        #pragma unroll
        for (int ks = 0; ks < 4; ++ks) {
            const int k0 = ks * 16;
            uint32_t bfr[4][2];
            #pragma unroll
            for (int nt2 = 0; nt2 < 2; ++nt2) {
                uint32_t r[4];
                ldm_x4(r, uB + (uint32_t)(b_row_off + nt2 * 16 * RS + k0) * 2);
                bfr[nt2 * 2 + 0][0] = r[0]; bfr[nt2 * 2 + 0][1] = r[1];
                bfr[nt2 * 2 + 1][0] = r[2]; bfr[nt2 * 2 + 1][1] = r[3];
            }
            uint32_t afr[2][4];
            #pragma unroll
            for (int mt = 0; mt < 2; ++mt)
                ldm_x4(afr[mt], uA + (uint32_t)(a_row_off + mt * 16 * RS + k0) * 2);
            #pragma unroll
            for (int mt = 0; mt < 2; ++mt)
                #pragma unroll
                for (int nt = 0; nt < 4; ++nt)
                    mma16816(acc[mt][nt], afr[mt], bfr[nt]);
        }
    };

    const int NC = ch.n;
    load_chunk(0, 0);
    for (int c = 0; c < NC; ++c) {
        if (c + 1 < NC) {
            load_chunk(c + 1, (c + 1) & 1);
            asm volatile("cp.async.wait_group 1;" ::: "memory");
        } else {
            asm volatile("cp.async.wait_group 0;" ::: "memory");
        }
        __syncthreads();
        compute(c & 1);
        __syncthreads();
    }

    const bool has_bn = (bn_gamma != nullptr);
    const int mrow = m0 + warp_m * 32 + (lane >> 2);
    const int ncol = warp_n * 32 + 2 * (lane & 3);
    #pragma unroll
    for (int mt = 0; mt < 2; ++mt) {
        #pragma unroll
        for (int half = 0; half < 2; ++half) {
            int gr = mrow + mt * 16 + half * 8;
            if (gr >= M) continue;
            #pragma unroll
            for (int nt = 0; nt < 4; ++nt) {
                int col = ncol + nt * 8;
                float x0 = acc[mt][nt][half * 2 + 0];
                float x1 = acc[mt][nt][half * 2 + 1];
                if (bias) { x0 += __ldg(bias + col); x1 += __ldg(bias + col + 1); }
                if (has_bn) {
                    float g0 = __ldg(bn_gamma + col), g1 = __ldg(bn_gamma + col + 1);
                    float be0 = __ldg(bn_beta + col), be1 = __ldg(bn_beta + col + 1);
                    float mn0 = __ldg(bn_mean + col), mn1 = __ldg(bn_mean + col + 1);
                    float vr0 = __ldg(bn_var + col), vr1 = __ldg(bn_var + col + 1);
                    x0 = fmaxf(g0 * (x0 - mn0) * rsqrtf(vr0 + BN_EPS) + be0, 0.f);
                    x1 = fmaxf(g1 * (x1 - mn1) * rsqrtf(vr1 + BN_EPS) + be1, 0.f);
                }
                if (Cf) {
                    float2 o; o.x = x0; o.y = x1;
                    *(float2*)(Cf + (size_t)gr * DD + col) = o;
                }
                if (Chi)
                    *(uint32_t*)(Chi + (size_t)gr * DD + col) = pack2h(x0, x1);
            }
        }
    }
}

// ================= fused prep =================
#define PB_SPLIT 6250                  // NN*32/256 (float4 granules)
#define PB_COUNT (PB_SPLIT + 3125)     // EE/256
#define PB_WEMB  (PB_COUNT + 64)       // DD*DD/256
#define PB_BC0   (PB_WEMB + 320)       // DD*KCAT/256
#define PB_BC1   (PB_BC0 + 320)

__global__ __launch_bounds__(256)
void prep_kernel(const float* __restrict__ node_feat, const float* __restrict__ W_emb,
                 const float* __restrict__ bases, const float* __restrict__ self_loop,
                 const int* __restrict__ dst, const int* __restrict__ etype,
                 int* __restrict__ cnt,
                 __half* __restrict__ nf_h,
                 __half* __restrict__ We_h,
                 __half* __restrict__ Bc0_h, __half* __restrict__ Bc1_h) {
    int b = blockIdx.x;
    int t = threadIdx.x;
    if (b < PB_SPLIT) {
        int i = b * 256 + t;
        float4 v = ((const float4*)node_feat)[i];
        ((uint2*)nf_h)[i] = pack4h(v);
    } else if (b < PB_COUNT) {
        int e = (b - PB_SPLIT) * 256 + t;
        if (e < EE) atomicAdd(&cnt[(size_t)dst[e] * RR + etype[e]], 1);
    } else if (b < PB_WEMB) {
        int i = (b - PB_COUNT) * 256 + t;
        int n = i >> 7, k = i & 127;
        We_h[i] = __float2half_rn(W_emb[(size_t)k * DD + n]);
    } else {
        int l = (b < PB_BC0) ? 0 : 1;
        int i = (b - (l ? PB_BC0 : PB_WEMB)) * 256 + t;
        int n = i / KCAT, k = i - n * KCAT;
        float v;
        if (k < 512) {
            int bb = k >> 7, d = k & 127;
            v = bases[(size_t)l * BB * DD * DD + (size_t)bb * DD * DD + (size_t)d * DD + n];
        } else {
            v = self_loop[(size_t)l * DD * DD + (size_t)(k - 512) * DD + n];
        }
        __half h = __float2half_rn(v);
        if (l == 0) Bc0_h[i] = h;
        else        Bc1_h[i] = h;
    }
}

// norm + deg + per-block deg sum (node-major cnt: two int4 loads per node)
__global__ __launch_bounds__(256) void normd_kernel(const int* __restrict__ cnt,
                                                    float* __restrict__ nodenorm,
                                                    int* __restrict__ deg,
                                                    int* __restrict__ bsum) {
    __shared__ int s[256];
    int n = blockIdx.x * 256 + threadIdx.x;
    int d = 0;
    if (n < NN) {
        int4 c0 = ((const int4*)cnt)[(size_t)n * 2 + 0];   // r = 0..3
        int4 c1 = ((const int4*)cnt)[(size_t)n * 2 + 1];   // r = 4..7
        int cr[8] = {c0.x, c0.y, c0.z, c0.w, c1.x, c1.y, c1.z, c1.w};
        float v = 0.f;
        bool found = false;
        #pragma unroll
        for (int r = RR - 1; r >= 0; --r) {
            int c = cr[r];
            d += c;
            if (!found && c > 0) { v = 1.0f / (float)c; found = true; }
        }
        nodenorm[n] = v;
        deg[n] = d;
    }
    s[threadIdx.x] = d;
    __syncthreads();
    for (int o = 128; o > 0; o >>= 1) {
        if (threadIdx.x < o) s[threadIdx.x] += s[threadIdx.x + o];
        __syncthreads();
    }
    if (threadIdx.x == 0) bsum[blockIdx.x] = s[0];
}

// rowptr/cursor; block offset computed in-block from raw bsum (nb <= 256)
__global__ void scan3(const int* __restrict__ deg, const int* __restrict__ bsum,
                      int* __restrict__ rowptr, int* __restrict__ cursor) {
    __shared__ int s[256];
    __shared__ int soff;
    int t = threadIdx.x;
    s[t] = (t < blockIdx.x) ? bsum[t] : 0;
    __syncthreads();
    for (int o = 128; o > 0; o >>= 1) {
        if (t < o) s[t] += s[t + o];
        __syncthreads();
    }
    if (t == 0) soff = s[0];
    __syncthreads();

    int i = blockIdx.x * 256 + t;
    int v = (i < NN) ? deg[i] : 0;
    s[t] = v;
    __syncthreads();
    for (int o = 1; o < 256; o <<= 1) {
        int u = (t >= o) ? s[t - o] : 0;
        __syncthreads();
        s[t] += u;
        __syncthreads();
    }
    int incl = s[t];
    if (i < NN) {
        rowptr[i] = soff + incl - v;
        cursor[i] = soff + incl - v;
        if (i == NN - 1) rowptr[NN] = soff + incl;
    }
}

__global__ __launch_bounds__(256) void fill_kernel(const int* __restrict__ src,
                                                   const int* __restrict__ dst,
                                                   const int* __restrict__ etype,
                                                   int* __restrict__ cursor,
                                                   int* __restrict__ edges) {
    int e = blockIdx.x * blockDim.x + threadIdx.x;
    if (e >= EE) return;
    int p = atomicAdd(&cursor[dst[e]], 1);
    edges[p] = src[e] | (etype[e] << 16);
}

// ================= gather: P_b[dst] = norm[dst] * sum_in w_coe[r,b] * h[src] =========
__global__ __launch_bounds__(256) void gather_kernel(const int* __restrict__ rowptr,
                                                     const int* __restrict__ edges,
                                                     const __half* __restrict__ hh,
                                                     const float* __restrict__ nodenorm,
                                                     const float* __restrict__ w_coe, int l,
                                                     __half* __restrict__ Phi) {
    __shared__ float swc[RR * BB];
    if (threadIdx.x < RR * BB) swc[threadIdx.x] = w_coe[l * RR * BB + threadIdx.x];
    __syncthreads();

    int gw = (blockIdx.x * 256 + threadIdx.x) >> 5;
    int lane = threadIdx.x & 31;
    if (gw >= NN) return;

    float4 a0 = make_float4(0.f, 0.f, 0.f, 0.f), a1 = a0, a2 = a0, a3 = a0;
    const int beg = rowptr[gw], end = rowptr[gw + 1];

    auto fetch = [&](int s) -> float4 {
        uint2 uh = *(const uint2*)(hh + (size_t)s * DD + lane * 4);
        __half2 h0 = *(__half2*)&uh.x, h1 = *(__half2*)&uh.y;
        float2 f0 = __half22float2(h0), f1 = __half22float2(h1);
        return make_float4(f0.x, f0.y, f1.x, f1.y);
    };
    auto accum = [&](int ev, float4 v) {
        int r = ev >> 16;
        float w0 = swc[r * 4 + 0], w1 = swc[r * 4 + 1];
        float w2 = swc[r * 4 + 2], w3 = swc[r * 4 + 3];
        a0.x += w0 * v.x; a0.y += w0 * v.y; a0.z += w0 * v.z; a0.w += w0 * v.w;
        a1.x += w1 * v.x; a1.y += w1 * v.y; a1.z += w1 * v.z; a1.w += w1 * v.w;
        a2.x += w2 * v.x; a2.y += w2 * v.y; a2.z += w2 * v.z; a2.w += w2 * v.w;
        a3.x += w3 * v.x; a3.y += w3 * v.y; a3.z += w3 * v.z; a3.w += w3 * v.w;
    };

    int i = beg;
    for (; i + 4 <= end; i += 4) {
        int e0 = edges[i], e1 = edges[i + 1], e2 = edges[i + 2], e3 = edges[i + 3];
        float4 v0 = fetch(e0 & 0xFFFF);
        float4 v1 = fetch(e1 & 0xFFFF);
        float4 v2 = fetch(e2 & 0xFFFF);
        float4 v3 = fetch(e3 & 0xFFFF);
        accum(e0, v0); accum(e1, v1); accum(e2, v2); accum(e3, v3);
    }
    for (; i < end; ++i) {
        int ev = edges[i];
        accum(ev, fetch(ev & 0xFFFF));
    }

    float nrm = nodenorm[gw];
    a0.x *= nrm; a0.y *= nrm; a0.z *= nrm; a0.w *= nrm;
    a1.x *= nrm; a1.y *= nrm; a1.z *= nrm; a1.w *= nrm;
    a2.x *= nrm; a2.y *= nrm; a2.z *= nrm; a2.w *= nrm;
    a3.x *= nrm; a3.y *= nrm; a3.z *= nrm; a3.w *= nrm;

    size_t base = (size_t)gw * 512 + lane * 4;
    *(uint2*)(Phi + base)       = pack4h(a0);
    *(uint2*)(Phi + base + 128) = pack4h(a1);
    *(uint2*)(Phi + base + 256) = pack4h(a2);
    *(uint2*)(Phi + base + 384) = pack4h(a3);
}

// ================= launcher =================
extern "C" void kernel_launch(void* const* d_in, const int* in_sizes, int n_in,
                              void* d_out, int out_size) {
    const float* node_feat = (const float*)d_in[0];
    const float* W_emb     = (const float*)d_in[1];
    const float* b_emb     = (const float*)d_in[2];
    const float* bases     = (const float*)d_in[3];
    const float* w_coe     = (const float*)d_in[4];
    const float* self_loop = (const float*)d_in[5];
    const float* bn_gamma  = (const float*)d_in[6];
    const float* bn_beta   = (const float*)d_in[7];
    const float* bn_mean   = (const float*)d_in[8];
    const float* bn_var    = (const float*)d_in[9];
    const int*   src       = (const int*)d_in[10];
    const int*   dst       = (const int*)d_in[11];
    const int*   etype     = (const int*)d_in[12];

    float* nodenorm;
    __half *hA, *hB, *nf, *P, *Bc_h, *We_h;
    int *cnt, *deg, *rowptr, *cursor, *bsum, *edges;
    cudaGetSymbolAddress((void**)&hA, g_hA);
    cudaGetSymbolAddress((void**)&hB, g_hB);
    cudaGetSymbolAddress((void**)&nf, g_nf);
    cudaGetSymbolAddress((void**)&P, g_P);
    cudaGetSymbolAddress((void**)&Bc_h, g_Bc_h);
    cudaGetSymbolAddress((void**)&We_h, g_We_h);
    cudaGetSymbolAddress((void**)&cnt, g_cnt);
    cudaGetSymbolAddress((void**)&nodenorm, g_nodenorm);
    cudaGetSymbolAddress((void**)&deg, g_deg);
    cudaGetSymbolAddress((void**)&rowptr, g_rowptr);
    cudaGetSymbolAddress((void**)&cursor, g_cursor);
    cudaGetSymbolAddress((void**)&bsum, g_bsum);
    cudaGetSymbolAddress((void**)&edges, g_edges);

    cudaFuncSetAttribute(mma_gemm, cudaFuncAttributeMaxDynamicSharedMemorySize, SMEM_GEMM_TOTAL);

    const int NB = (NN + 255) / 256;   // 196
    dim3 ggrid(1, (NN + 63) / 64);     // 782 tiles

    cudaMemsetAsync(cnt, 0, (size_t)NN * RR * sizeof(int));
    prep_kernel<<<PB_BC1, 256>>>(node_feat, W_emb, bases, self_loop, dst, etype, cnt,
                                 nf, We_h,
                                 &Bc_h[0], &Bc_h[(size_t)DD * KCAT]);
    // embedding GEMM: hA = fp16(nf @ W_emb + b_emb)
    {
        GemmChunks ce = {};
        ce.n = 2;
        for (int c = 0; c < 2; ++c) {
            ce.c[c].Ah = nf + c * KCH;   ce.c[c].lda = DD;
            ce.c[c].Bh = We_h + c * KCH; ce.c[c].ldb = DD;
        }
        mma_gemm<<<ggrid, 256, SMEM_GEMM_TOTAL>>>(ce, b_emb, nullptr, nullptr, nullptr, nullptr,
                                                  nullptr, hA, NN);
    }
    normd_kernel<<<NB, 256>>>(cnt, nodenorm, deg, bsum);
    scan3<<<NB, 256>>>(deg, bsum, rowptr, cursor);
    fill_kernel<<<(EE + 255) / 256, 256>>>(src, dst, etype, cursor, edges);

    for (int l = 0; l < LL; ++l) {
        __half* hin  = l ? hB : hA;
        __half* hout = l ? nullptr : hB;            // last layer: no fp16 out
        float*  houf = l ? (float*)d_out : nullptr; // last layer: write d_out directly
        __half* bch = Bc_h + (size_t)l * DD * KCAT;

        gather_kernel<<<(NN * 32 + 255) / 256, 256>>>(rowptr, edges, hin, nodenorm,
                                                      w_coe, l, P);
        GemmChunks cl = {};
        cl.n = 10;
        for (int c = 0; c < 10; ++c) {
            if (c < 8) { cl.c[c].Ah = P + c * KCH;            cl.c[c].lda = 512; }
            else       { cl.c[c].Ah = hin + (c - 8) * KCH;    cl.c[c].lda = DD;  }
            cl.c[c].Bh  = bch + c * KCH;
            cl.c[c].ldb = KCAT;
        }
        mma_gemm<<<ggrid, 256, SMEM_GEMM_TOTAL>>>(cl, nullptr,
                                                  bn_gamma + (size_t)l * DD,
                                                  bn_beta  + (size_t)l * DD,
                                                  bn_mean  + (size_t)l * DD,
                                                  bn_var   + (size_t)l * DD,
                                                  houf, hout, NN);
    }
}

// round 16
// speedup vs baseline: 1.4846x; 1.4846x over previous
#include <cuda_runtime.h>
#include <cuda_fp16.h>
#include <cstdint>
#include <cstddef>

#define NN 50000
#define EE 800000
#define DD 128
#define RR 8
#define BB 4
#define LL 2
#define KCAT 640               // 4 bases * 128 + 128 self-loop
#define BN_EPS 1e-3f

#define KCH 64                 // k-chunk depth
#define RS 72                  // smem row stride (elements), 144B
#define TILE_A_E (64 * RS)     // 64-row A tile
#define TILE_B_E (128 * RS)    // 128-row B tile
#define STAGE_E (TILE_A_E + TILE_B_E)       // A, B
#define SMEM_GEMM_TOTAL (2 * STAGE_E * 2)   // 55296 bytes (2 stages)

// ---------------- device scratch ----------------
__device__ __half  g_hA[(size_t)NN * DD];
__device__ __half  g_hB[(size_t)NN * DD];
__device__ __half  g_nf[(size_t)NN * DD];
__device__ __half  g_P[(size_t)NN * 512];
__device__ __half  g_Bc_h[2][(size_t)DD * KCAT];
__device__ __half  g_We_h[(size_t)DD * DD];
__device__ int     g_cnt[(size_t)RR * NN];
__device__ float   g_nodenorm[NN];
__device__ int     g_deg[NN];
__device__ int     g_rowptr[NN + 1];
__device__ int     g_cursor[NN];
__device__ int     g_bsum[256];
__device__ int     g_edges[EE];

// ================= helpers =================
__device__ __forceinline__ uint32_t smem_u32(const void* p) {
    uint32_t a;
    asm("{ .reg .u64 t; cvta.to.shared.u64 t, %1; cvt.u32.u64 %0, t; }" : "=r"(a) : "l"(p));
    return a;
}
__device__ __forceinline__ void ldm_x4(uint32_t* r, uint32_t addr) {
    asm volatile("ldmatrix.sync.aligned.m8n8.x4.shared.b16 {%0,%1,%2,%3}, [%4];"
                 : "=r"(r[0]), "=r"(r[1]), "=r"(r[2]), "=r"(r[3]) : "r"(addr));
}
__device__ __forceinline__ void mma16816(float* d, const uint32_t* a, const uint32_t* b) {
    asm volatile("mma.sync.aligned.m16n8k16.row.col.f32.f16.f16.f32 "
                 "{%0,%1,%2,%3}, {%4,%5,%6,%7}, {%8,%9}, {%0,%1,%2,%3};"
                 : "+f"(d[0]), "+f"(d[1]), "+f"(d[2]), "+f"(d[3])
                 : "r"(a[0]), "r"(a[1]), "r"(a[2]), "r"(a[3]), "r"(b[0]), "r"(b[1]));
}
__device__ __forceinline__ void cp_async16(uint32_t d, const void* s, int sz) {
    asm volatile("cp.async.cg.shared.global [%0], [%1], 16, %2;"
                 :: "r"(d), "l"(__cvta_generic_to_global(s)), "r"(sz));
}
__device__ __forceinline__ uint32_t pack2h(float x0, float x1) {
    __half2 a = __floats2half2_rn(x0, x1);
    return *(uint32_t*)&a;
}
__device__ __forceinline__ uint2 pack4h(float4 v) {
    uint2 r;
    r.x = pack2h(v.x, v.y);
    r.y = pack2h(v.z, v.w);
    return r;
}

// ================= GEMM (HMMA fp16, single-term, 64x128 tiles) =========
struct Chunk { const __half *Ah, *Bh; int lda, ldb; };
struct GemmChunks { int n; Chunk c[10]; };

__global__ __launch_bounds__(256, 3)
void mma_gemm(GemmChunks ch,
              const float* __restrict__ bias,
              const float* __restrict__ bn_gamma, const float* __restrict__ bn_beta,
              const float* __restrict__ bn_mean, const float* __restrict__ bn_var,
              float* __restrict__ Cf, __half* __restrict__ Chi, int M) {
    extern __shared__ __half smem[];
    const int tid = threadIdx.x;
    const int wid = tid >> 5;
    const int lane = tid & 31;
    const int warp_m = wid >> 2;          // 0..1, 32 rows each
    const int warp_n = wid & 3;           // 0..3, 32 cols each
    const int m0 = blockIdx.y * 64;

    auto load_chunk = [&](int c, int st) {
        const Chunk ck = ch.c[c];
        __half* s0 = smem + st * STAGE_E;
        #pragma unroll
        for (int i = 0; i < 2; ++i) {
            int t = tid + i * 256;          // 0..511
            int row = t >> 3, kc = t & 7;
            int gr = m0 + row;
            int ok = (gr < M);
            size_t ga = (size_t)(ok ? gr : 0);
            cp_async16(smem_u32(s0 + row * RS + kc * 8),
                       ck.Ah + ga * ck.lda + kc * 8, ok ? 16 : 0);
        }
        #pragma unroll
        for (int i = 0; i < 4; ++i) {
            int t = tid + i * 256;
            int row = t >> 3, kc = t & 7;
            cp_async16(smem_u32(s0 + TILE_A_E + row * RS + kc * 8),
                       ck.Bh + (size_t)row * ck.ldb + kc * 8, 16);
        }
        asm volatile("cp.async.commit_group;" ::: "memory");
    };

    float acc[2][4][4];
    #pragma unroll
    for (int a = 0; a < 2; ++a)
        #pragma unroll
        for (int b = 0; b < 4; ++b)
            #pragma unroll
            for (int c = 0; c < 4; ++c) acc[a][b][c] = 0.f;

    const int a_row_off = (warp_m * 32 + (lane & 15)) * RS + ((lane >> 4) << 3);
    const int b_row_off = (warp_n * 32 + (lane & 7) + (((lane >> 4) & 1) << 3)) * RS
                          + (((lane >> 3) & 1) << 3);

    auto compute = [&](int st) {
        const uint32_t ub = smem_u32(smem + st * STAGE_E);
        const uint32_t uA = ub;
        const uint32_t uB = ub + (uint32_t)TILE_A_E * 2u;
        #pragma unroll
        for (int ks = 0; ks < 4; ++ks) {
            const int k0 = ks * 16;
            uint32_t bfr[4][2];
            #pragma unroll
            for (int nt2 = 0; nt2 < 2; ++nt2) {
                uint32_t r[4];
                ldm_x4(r, uB + (uint32_t)(b_row_off + nt2 * 16 * RS + k0) * 2);
                bfr[nt2 * 2 + 0][0] = r[0]; bfr[nt2 * 2 + 0][1] = r[1];
                bfr[nt2 * 2 + 1][0] = r[2]; bfr[nt2 * 2 + 1][1] = r[3];
            }
            uint32_t afr[2][4];
            #pragma unroll
            for (int mt = 0; mt < 2; ++mt)
                ldm_x4(afr[mt], uA + (uint32_t)(a_row_off + mt * 16 * RS + k0) * 2);
            #pragma unroll
            for (int mt = 0; mt < 2; ++mt)
                #pragma unroll
                for (int nt = 0; nt < 4; ++nt)
                    mma16816(acc[mt][nt], afr[mt], bfr[nt]);
        }
    };

    const int NC = ch.n;
    load_chunk(0, 0);
    for (int c = 0; c < NC; ++c) {
        if (c + 1 < NC) {
            load_chunk(c + 1, (c + 1) & 1);
            asm volatile("cp.async.wait_group 1;" ::: "memory");
        } else {
            asm volatile("cp.async.wait_group 0;" ::: "memory");
        }
        __syncthreads();
        compute(c & 1);
        __syncthreads();
    }

    const bool has_bn = (bn_gamma != nullptr);
    const int mrow = m0 + warp_m * 32 + (lane >> 2);
    const int ncol = warp_n * 32 + 2 * (lane & 3);
    #pragma unroll
    for (int mt = 0; mt < 2; ++mt) {
        #pragma unroll
        for (int half = 0; half < 2; ++half) {
            int gr = mrow + mt * 16 + half * 8;
            if (gr >= M) continue;
            #pragma unroll
            for (int nt = 0; nt < 4; ++nt) {
                int col = ncol + nt * 8;
                float x0 = acc[mt][nt][half * 2 + 0];
                float x1 = acc[mt][nt][half * 2 + 1];
                if (bias) { x0 += __ldg(bias + col); x1 += __ldg(bias + col + 1); }
                if (has_bn) {
                    float g0 = __ldg(bn_gamma + col), g1 = __ldg(bn_gamma + col + 1);
                    float be0 = __ldg(bn_beta + col), be1 = __ldg(bn_beta + col + 1);
                    float mn0 = __ldg(bn_mean + col), mn1 = __ldg(bn_mean + col + 1);
                    float vr0 = __ldg(bn_var + col), vr1 = __ldg(bn_var + col + 1);
                    x0 = fmaxf(g0 * (x0 - mn0) * rsqrtf(vr0 + BN_EPS) + be0, 0.f);
                    x1 = fmaxf(g1 * (x1 - mn1) * rsqrtf(vr1 + BN_EPS) + be1, 0.f);
                }
                if (Cf) {
                    float2 o; o.x = x0; o.y = x1;
                    *(float2*)(Cf + (size_t)gr * DD + col) = o;
                }
                if (Chi)
                    *(uint32_t*)(Chi + (size_t)gr * DD + col) = pack2h(x0, x1);
            }
        }
    }
}

// ================= fused prep =================
#define PB_SPLIT 6250                  // NN*32/256 (float4 granules)
#define PB_COUNT (PB_SPLIT + 3125)     // EE/256
#define PB_WEMB  (PB_COUNT + 64)       // DD*DD/256
#define PB_BC0   (PB_WEMB + 320)       // DD*KCAT/256
#define PB_BC1   (PB_BC0 + 320)

__global__ __launch_bounds__(256)
void prep_kernel(const float* __restrict__ node_feat, const float* __restrict__ W_emb,
                 const float* __restrict__ bases, const float* __restrict__ self_loop,
                 const int* __restrict__ dst, const int* __restrict__ etype,
                 int* __restrict__ cnt,
                 __half* __restrict__ nf_h,
                 __half* __restrict__ We_h,
                 __half* __restrict__ Bc0_h, __half* __restrict__ Bc1_h) {
    int b = blockIdx.x;
    int t = threadIdx.x;
    if (b < PB_SPLIT) {
        int i = b * 256 + t;
        float4 v = ((const float4*)node_feat)[i];
        ((uint2*)nf_h)[i] = pack4h(v);
    } else if (b < PB_COUNT) {
        int e = (b - PB_SPLIT) * 256 + t;
        if (e < EE) atomicAdd(&cnt[(size_t)etype[e] * NN + dst[e]], 1);
    } else if (b < PB_WEMB) {
        int i = (b - PB_COUNT) * 256 + t;
        int n = i >> 7, k = i & 127;
        We_h[i] = __float2half_rn(W_emb[(size_t)k * DD + n]);
    } else {
        int l = (b < PB_BC0) ? 0 : 1;
        int i = (b - (l ? PB_BC0 : PB_WEMB)) * 256 + t;
        int n = i / KCAT, k = i - n * KCAT;
        float v;
        if (k < 512) {
            int bb = k >> 7, d = k & 127;
            v = bases[(size_t)l * BB * DD * DD + (size_t)bb * DD * DD + (size_t)d * DD + n];
        } else {
            v = self_loop[(size_t)l * DD * DD + (size_t)(k - 512) * DD + n];
        }
        __half h = __float2half_rn(v);
        if (l == 0) Bc0_h[i] = h;
        else        Bc1_h[i] = h;
    }
}

__global__ __launch_bounds__(256) void normd_kernel(const int* __restrict__ cnt,
                                                    float* __restrict__ nodenorm,
                                                    int* __restrict__ deg,
                                                    int* __restrict__ bsum) {
    __shared__ int s[256];
    int n = blockIdx.x * 256 + threadIdx.x;
    int d = 0;
    if (n < NN) {
        float v = 0.f;
        bool found = false;
        #pragma unroll
        for (int r = RR - 1; r >= 0; --r) {
            int c = cnt[(size_t)r * NN + n];
            d += c;
            if (!found && c > 0) { v = 1.0f / (float)c; found = true; }
        }
        nodenorm[n] = v;
        deg[n] = d;
    }
    s[threadIdx.x] = d;
    __syncthreads();
    for (int o = 128; o > 0; o >>= 1) {
        if (threadIdx.x < o) s[threadIdx.x] += s[threadIdx.x + o];
        __syncthreads();
    }
    if (threadIdx.x == 0) bsum[blockIdx.x] = s[0];
}

// rowptr/cursor; block offset computed in-block from raw bsum (nb <= 256)
__global__ void scan3(const int* __restrict__ deg, const int* __restrict__ bsum,
                      int* __restrict__ rowptr, int* __restrict__ cursor) {
    __shared__ int s[256];
    __shared__ int soff;
    int t = threadIdx.x;
    s[t] = (t < blockIdx.x) ? bsum[t] : 0;
    __syncthreads();
    for (int o = 128; o > 0; o >>= 1) {
        if (t < o) s[t] += s[t + o];
        __syncthreads();
    }
    if (t == 0) soff = s[0];
    __syncthreads();

    int i = blockIdx.x * 256 + t;
    int v = (i < NN) ? deg[i] : 0;
    s[t] = v;
    __syncthreads();
    for (int o = 1; o < 256; o <<= 1) {
        int u = (t >= o) ? s[t - o] : 0;
        __syncthreads();
        s[t] += u;
        __syncthreads();
    }
    int incl = s[t];
    if (i < NN) {
        rowptr[i] = soff + incl - v;
        cursor[i] = soff + incl - v;
        if (i == NN - 1) rowptr[NN] = soff + incl;
    }
}

__global__ __launch_bounds__(256) void fill_kernel(const int* __restrict__ src,
                                                   const int* __restrict__ dst,
                                                   const int* __restrict__ etype,
                                                   int* __restrict__ cursor,
                                                   int* __restrict__ edges) {
    int e = blockIdx.x * blockDim.x + threadIdx.x;
    if (e >= EE) return;
    int p = atomicAdd(&cursor[dst[e]], 1);
    edges[p] = src[e] | (etype[e] << 16);
}

// ================= gather: P_b[dst] = norm[dst] * sum_in w_coe[r,b] * h[src] =========
__global__ __launch_bounds__(256) void gather_kernel(const int* __restrict__ rowptr,
                                                     const int* __restrict__ edges,
                                                     const __half* __restrict__ hh,
                                                     const float* __restrict__ nodenorm,
                                                     const float* __restrict__ w_coe, int l,
                                                     __half* __restrict__ Phi) {
    __shared__ float swc[RR * BB];
    if (threadIdx.x < RR * BB) swc[threadIdx.x] = w_coe[l * RR * BB + threadIdx.x];
    __syncthreads();

    int gw = (blockIdx.x * 256 + threadIdx.x) >> 5;
    int lane = threadIdx.x & 31;
    if (gw >= NN) return;

    float4 a0 = make_float4(0.f, 0.f, 0.f, 0.f), a1 = a0, a2 = a0, a3 = a0;
    const int beg = rowptr[gw], end = rowptr[gw + 1];

    auto fetch = [&](int s) -> float4 {
        uint2 uh = *(const uint2*)(hh + (size_t)s * DD + lane * 4);
        __half2 h0 = *(__half2*)&uh.x, h1 = *(__half2*)&uh.y;
        float2 f0 = __half22float2(h0), f1 = __half22float2(h1);
        return make_float4(f0.x, f0.y, f1.x, f1.y);
    };
    auto accum = [&](int ev, float4 v) {
        int r = ev >> 16;
        float w0 = swc[r * 4 + 0], w1 = swc[r * 4 + 1];
        float w2 = swc[r * 4 + 2], w3 = swc[r * 4 + 3];
        a0.x += w0 * v.x; a0.y += w0 * v.y; a0.z += w0 * v.z; a0.w += w0 * v.w;
        a1.x += w1 * v.x; a1.y += w1 * v.y; a1.z += w1 * v.z; a1.w += w1 * v.w;
        a2.x += w2 * v.x; a2.y += w2 * v.y; a2.z += w2 * v.z; a2.w += w2 * v.w;
        a3.x += w3 * v.x; a3.y += w3 * v.y; a3.z += w3 * v.z; a3.w += w3 * v.w;
    };

    int i = beg;
    for (; i + 4 <= end; i += 4) {
        int e0 = edges[i], e1 = edges[i + 1], e2 = edges[i + 2], e3 = edges[i + 3];
        float4 v0 = fetch(e0 & 0xFFFF);
        float4 v1 = fetch(e1 & 0xFFFF);
        float4 v2 = fetch(e2 & 0xFFFF);
        float4 v3 = fetch(e3 & 0xFFFF);
        accum(e0, v0); accum(e1, v1); accum(e2, v2); accum(e3, v3);
    }
    for (; i < end; ++i) {
        int ev = edges[i];
        accum(ev, fetch(ev & 0xFFFF));
    }

    float nrm = nodenorm[gw];
    a0.x *= nrm; a0.y *= nrm; a0.z *= nrm; a0.w *= nrm;
    a1.x *= nrm; a1.y *= nrm; a1.z *= nrm; a1.w *= nrm;
    a2.x *= nrm; a2.y *= nrm; a2.z *= nrm; a2.w *= nrm;
    a3.x *= nrm; a3.y *= nrm; a3.z *= nrm; a3.w *= nrm;

    size_t base = (size_t)gw * 512 + lane * 4;
    *(uint2*)(Phi + base)       = pack4h(a0);
    *(uint2*)(Phi + base + 128) = pack4h(a1);
    *(uint2*)(Phi + base + 256) = pack4h(a2);
    *(uint2*)(Phi + base + 384) = pack4h(a3);
}

// ================= launcher =================
extern "C" void kernel_launch(void* const* d_in, const int* in_sizes, int n_in,
                              void* d_out, int out_size) {
    const float* node_feat = (const float*)d_in[0];
    const float* W_emb     = (const float*)d_in[1];
    const float* b_emb     = (const float*)d_in[2];
    const float* bases     = (const float*)d_in[3];
    const float* w_coe     = (const float*)d_in[4];
    const float* self_loop = (const float*)d_in[5];
    const float* bn_gamma  = (const float*)d_in[6];
    const float* bn_beta   = (const float*)d_in[7];
    const float* bn_mean   = (const float*)d_in[8];
    const float* bn_var    = (const float*)d_in[9];
    const int*   src       = (const int*)d_in[10];
    const int*   dst       = (const int*)d_in[11];
    const int*   etype     = (const int*)d_in[12];

    float* nodenorm;
    __half *hA, *hB, *nf, *P, *Bc_h, *We_h;
    int *cnt, *deg, *rowptr, *cursor, *bsum, *edges;
    cudaGetSymbolAddress((void**)&hA, g_hA);
    cudaGetSymbolAddress((void**)&hB, g_hB);
    cudaGetSymbolAddress((void**)&nf, g_nf);
    cudaGetSymbolAddress((void**)&P, g_P);
    cudaGetSymbolAddress((void**)&Bc_h, g_Bc_h);
    cudaGetSymbolAddress((void**)&We_h, g_We_h);
    cudaGetSymbolAddress((void**)&cnt, g_cnt);
    cudaGetSymbolAddress((void**)&nodenorm, g_nodenorm);
    cudaGetSymbolAddress((void**)&deg, g_deg);
    cudaGetSymbolAddress((void**)&rowptr, g_rowptr);
    cudaGetSymbolAddress((void**)&cursor, g_cursor);
    cudaGetSymbolAddress((void**)&bsum, g_bsum);
    cudaGetSymbolAddress((void**)&edges, g_edges);

    cudaFuncSetAttribute(mma_gemm, cudaFuncAttributeMaxDynamicSharedMemorySize, SMEM_GEMM_TOTAL);

    const int NB = (NN + 255) / 256;   // 196
    dim3 ggrid(1, (NN + 63) / 64);     // 782 tiles

    cudaMemsetAsync(cnt, 0, (size_t)RR * NN * sizeof(int));
    prep_kernel<<<PB_BC1, 256>>>(node_feat, W_emb, bases, self_loop, dst, etype, cnt,
                                 nf, We_h,
                                 &Bc_h[0], &Bc_h[(size_t)DD * KCAT]);
    // embedding GEMM: hA = fp16(nf @ W_emb + b_emb)
    {
        GemmChunks ce = {};
        ce.n = 2;
        for (int c = 0; c < 2; ++c) {
            ce.c[c].Ah = nf + c * KCH;   ce.c[c].lda = DD;
            ce.c[c].Bh = We_h + c * KCH; ce.c[c].ldb = DD;
        }
        mma_gemm<<<ggrid, 256, SMEM_GEMM_TOTAL>>>(ce, b_emb, nullptr, nullptr, nullptr, nullptr,
                                                  nullptr, hA, NN);
    }
    normd_kernel<<<NB, 256>>>(cnt, nodenorm, deg, bsum);
    scan3<<<NB, 256>>>(deg, bsum, rowptr, cursor);
    fill_kernel<<<(EE + 255) / 256, 256>>>(src, dst, etype, cursor, edges);

    for (int l = 0; l < LL; ++l) {
        __half* hin  = l ? hB : hA;
        __half* hout = l ? nullptr : hB;            // last layer: no fp16 out
        float*  houf = l ? (float*)d_out : nullptr; // last layer: write d_out directly
        __half* bch = Bc_h + (size_t)l * DD * KCAT;

        gather_kernel<<<(NN * 32 + 255) / 256, 256>>>(rowptr, edges, hin, nodenorm,
                                                      w_coe, l, P);
        GemmChunks cl = {};
        cl.n = 10;
        for (int c = 0; c < 10; ++c) {
            if (c < 8) { cl.c[c].Ah = P + c * KCH;            cl.c[c].lda = 512; }
            else       { cl.c[c].Ah = hin + (c - 8) * KCH;    cl.c[c].lda = DD;  }
            cl.c[c].Bh  = bch + c * KCH;
            cl.c[c].ldb = KCAT;
        }
        mma_gemm<<<ggrid, 256, SMEM_GEMM_TOTAL>>>(cl, nullptr,
                                                  bn_gamma + (size_t)l * DD,
                                                  bn_beta  + (size_t)l * DD,
                                                  bn_mean  + (size_t)l * DD,
                                                  bn_var   + (size_t)l * DD,
                                                  houf, hout, NN);
    }
}